// round 1
// baseline (speedup 1.0000x reference)
#include <cuda_runtime.h>

#define T_LEN 2048

// ---- fast-but-accurate transcendentals (MUFU.EX2 / MUFU.RCP, ~2^-22 rel err) ----
__device__ __forceinline__ float ex2f(float x) {
    float y; asm("ex2.approx.f32 %0, %1;" : "=f"(y) : "f"(x)); return y;
}
__device__ __forceinline__ float rcpf(float x) {
    float y; asm("rcp.approx.f32 %0, %1;" : "=f"(y) : "f"(x)); return y;
}
// sigmoid(x) = 1/(1+exp(-x)); exp(-x) = 2^(-x*log2e). Saturates correctly at +-inf.
__device__ __forceinline__ float sigmoidf_(float x) {
    return rcpf(1.0f + ex2f(-1.4426950408889634f * x));
}
// tanh(x) = 1 - 2/(exp(2x)+1). Saturates correctly at +-inf.
__device__ __forceinline__ float tanhf_(float x) {
    float e = ex2f(2.8853900817779268f * x);
    return fmaf(-2.0f, rcpf(e + 1.0f), 1.0f);
}

// dot over 8 with two parallel 4-chains (latency ~24cyc instead of ~36)
__device__ __forceinline__ float dot8(const float w[8], const float h[8], float acc) {
    float a = fmaf(w[0], h[0], fmaf(w[1], h[1], fmaf(w[2], h[2], w[3] * h[3])));
    float b = fmaf(w[4], h[4], fmaf(w[5], h[5], fmaf(w[6], h[6], w[7] * h[7])));
    return acc + a + b;
}

// 8 lanes per batch element. Lane j owns gate rows {j, j+8, j+16, j+24} of both
// layers and the states c1_j, c2_j. h1/h2 are replicated into every lane of the
// 8-lane group (8 SHFL.IDX per layer per timestep).
__global__ void __launch_bounds__(128) lstm2_fused_kernel(
    const float* __restrict__ x,
    const float* __restrict__ w_ih1, const float* __restrict__ w_hh1,
    const float* __restrict__ b_ih1, const float* __restrict__ b_hh1,
    const float* __restrict__ w_ih2, const float* __restrict__ w_hh2,
    const float* __restrict__ b_ih2, const float* __restrict__ b_hh2,
    const float* __restrict__ fc_w, const float* __restrict__ fc_b,
    float* __restrict__ out, int B)
{
    const int tid  = blockIdx.x * blockDim.x + threadIdx.x;
    const int b    = tid >> 3;            // batch element
    if (b >= B) return;                   // grid sized exactly; full warps only
    const int j    = tid & 7;             // hidden row owned by this lane
    const int lane = threadIdx.x & 31;
    const int base = lane & 24;           // first lane of this 8-lane group
    const unsigned FULL = 0xffffffffu;

    const int gi = j, gf = j + 8, gg = j + 16, go = j + 24;

    // ---- load per-lane weights into registers (one-time) ----
    float wx1[4];                          // w_ih1 is (32,1): scalar per gate
    wx1[0] = w_ih1[gi]; wx1[1] = w_ih1[gf]; wx1[2] = w_ih1[gg]; wx1[3] = w_ih1[go];
    float bb1[4];
    bb1[0] = b_ih1[gi] + b_hh1[gi];
    bb1[1] = b_ih1[gf] + b_hh1[gf];
    bb1[2] = b_ih1[gg] + b_hh1[gg];
    bb1[3] = b_ih1[go] + b_hh1[go];
    float bb2[4];
    bb2[0] = b_ih2[gi] + b_hh2[gi];
    bb2[1] = b_ih2[gf] + b_hh2[gf];
    bb2[2] = b_ih2[gg] + b_hh2[gg];
    bb2[3] = b_ih2[go] + b_hh2[go];

    float wh1[4][8], wx2[4][8], wh2[4][8];
    #pragma unroll
    for (int k = 0; k < 8; k++) {
        wh1[0][k] = w_hh1[gi * 8 + k];
        wh1[1][k] = w_hh1[gf * 8 + k];
        wh1[2][k] = w_hh1[gg * 8 + k];
        wh1[3][k] = w_hh1[go * 8 + k];
        wx2[0][k] = w_ih2[gi * 8 + k];
        wx2[1][k] = w_ih2[gf * 8 + k];
        wx2[2][k] = w_ih2[gg * 8 + k];
        wx2[3][k] = w_ih2[go * 8 + k];
        wh2[0][k] = w_hh2[gi * 8 + k];
        wh2[1][k] = w_hh2[gf * 8 + k];
        wh2[2][k] = w_hh2[gg * 8 + k];
        wh2[3][k] = w_hh2[go * 8 + k];
    }

    // ---- state ----
    float h1[8], h2[8];
    #pragma unroll
    for (int k = 0; k < 8; k++) { h1[k] = 0.0f; h2[k] = 0.0f; }
    float c1 = 0.0f, c2 = 0.0f;

    const float* xb = x + (size_t)b * T_LEN;
    float xt_next = __ldg(&xb[0]);        // prefetch

    #pragma unroll 2
    for (int t = 0; t < T_LEN; t++) {
        const float xt = xt_next;
        xt_next = __ldg(&xb[(t + 1) & (T_LEN - 1)]);   // wraps harmlessly at end

        // -- layer2 recurrent partial: depends only on h2_{t-1}; overlaps layer1 --
        float z0 = dot8(wh2[0], h2, bb2[0]);
        float z1 = dot8(wh2[1], h2, bb2[1]);
        float z2 = dot8(wh2[2], h2, bb2[2]);
        float z3 = dot8(wh2[3], h2, bb2[3]);

        // -- layer1: gates = x*w_ih1 + b + W_hh1 . h1 --
        float a0 = dot8(wh1[0], h1, fmaf(xt, wx1[0], bb1[0]));
        float a1 = dot8(wh1[1], h1, fmaf(xt, wx1[1], bb1[1]));
        float a2 = dot8(wh1[2], h1, fmaf(xt, wx1[2], bb1[2]));
        float a3 = dot8(wh1[3], h1, fmaf(xt, wx1[3], bb1[3]));

        const float I1 = sigmoidf_(a0);
        const float F1 = sigmoidf_(a1);
        const float G1 = tanhf_(a2);
        const float O1 = sigmoidf_(a3);
        c1 = fmaf(F1, c1, I1 * G1);
        const float h1j = O1 * tanhf_(c1);

        #pragma unroll
        for (int k = 0; k < 8; k++)
            h1[k] = __shfl_sync(FULL, h1j, base + k);

        // -- layer2: gates = W_ih2 . h1_t + (precomputed recurrent partial) --
        float e0 = dot8(wx2[0], h1, z0);
        float e1 = dot8(wx2[1], h1, z1);
        float e2 = dot8(wx2[2], h1, z2);
        float e3 = dot8(wx2[3], h1, z3);

        const float I2 = sigmoidf_(e0);
        const float F2 = sigmoidf_(e1);
        const float G2 = tanhf_(e2);
        const float O2 = sigmoidf_(e3);
        c2 = fmaf(F2, c2, I2 * G2);
        const float h2j = O2 * tanhf_(c2);

        #pragma unroll
        for (int k = 0; k < 8; k++)
            h2[k] = __shfl_sync(FULL, h2j, base + k);
    }

    // ---- fc on final h2 (h2 fully replicated in every lane; lanes 0..3 of group write) ----
    if (j < 4) {
        float acc = fc_b[j];
        #pragma unroll
        for (int k = 0; k < 8; k++)
            acc = fmaf(fc_w[j * 8 + k], h2[k], acc);
        out[b * 4 + j] = acc;
    }
}

extern "C" void kernel_launch(void* const* d_in, const int* in_sizes, int n_in,
                              void* d_out, int out_size)
{
    const float* x     = (const float*)d_in[0];
    const float* w_ih1 = (const float*)d_in[1];
    const float* w_hh1 = (const float*)d_in[2];
    const float* b_ih1 = (const float*)d_in[3];
    const float* b_hh1 = (const float*)d_in[4];
    const float* w_ih2 = (const float*)d_in[5];
    const float* w_hh2 = (const float*)d_in[6];
    const float* b_ih2 = (const float*)d_in[7];
    const float* b_hh2 = (const float*)d_in[8];
    const float* fc_w  = (const float*)d_in[9];
    const float* fc_b  = (const float*)d_in[10];
    float* out = (float*)d_out;

    const int B = in_sizes[0] / T_LEN;      // 4096
    const int threads = B * 8;              // 8 lanes per batch element
    const int block = 128;                  // 16 batches / CTA -> 256 CTAs, one wave
    const int grid = (threads + block - 1) / block;

    lstm2_fused_kernel<<<grid, block>>>(x, w_ih1, w_hh1, b_ih1, b_hh1,
                                        w_ih2, w_hh2, b_ih2, b_hh2,
                                        fc_w, fc_b, out, B);
}

// round 2
// speedup vs baseline: 1.1549x; 1.1549x over previous
#include <cuda_runtime.h>

#define T_LEN 2048
typedef unsigned long long u64;

// ---- MUFU helpers ----
__device__ __forceinline__ float ex2f(float x){ float y; asm("ex2.approx.f32 %0, %1;" : "=f"(y) : "f"(x)); return y; }
__device__ __forceinline__ float rcpf(float x){ float y; asm("rcp.approx.f32 %0, %1;" : "=f"(y) : "f"(x)); return y; }

// ---- packed f32x2 helpers (sm_100+) ----
__device__ __forceinline__ u64 pk(float lo, float hi){ u64 d; asm("mov.b64 %0, {%1, %2};" : "=l"(d) : "f"(lo), "f"(hi)); return d; }
__device__ __forceinline__ void unpk(u64 d, float& lo, float& hi){ asm("mov.b64 {%0, %1}, %2;" : "=f"(lo), "=f"(hi) : "l"(d)); }
__device__ __forceinline__ u64 fma2_(u64 a, u64 b, u64 c){ u64 d; asm("fma.rn.f32x2 %0, %1, %2, %3;" : "=l"(d) : "l"(a), "l"(b), "l"(c)); return d; }
__device__ __forceinline__ u64 mul2_(u64 a, u64 b){ u64 d; asm("mul.rn.f32x2 %0, %1, %2;" : "=l"(d) : "l"(a), "l"(b)); return d; }
__device__ __forceinline__ u64 add2_(u64 a, u64 b){ u64 d; asm("add.rn.f32x2 %0, %1, %2;" : "=l"(d) : "l"(a), "l"(b)); return d; }

// 8 lanes per batch. Lane j owns hidden unit j of both layers: gate rows
// {j, j+8, j+16, j+24}, packed as (i,f) and (g,o) f32x2 pairs. Activation
// scale factors (-log2e for sigmoid rows, +2log2e for tanh rows) are folded
// into weights/biases. Layers are software-pipelined: iteration t computes
// L1(t) and L2(t-1) concurrently (both depend only on h1_{t-1}).
__global__ void __launch_bounds__(128) lstm2_fused_kernel(
    const float* __restrict__ x,
    const float* __restrict__ w_ih1, const float* __restrict__ w_hh1,
    const float* __restrict__ b_ih1, const float* __restrict__ b_hh1,
    const float* __restrict__ w_ih2, const float* __restrict__ w_hh2,
    const float* __restrict__ b_ih2, const float* __restrict__ b_hh2,
    const float* __restrict__ fc_w, const float* __restrict__ fc_b,
    float* __restrict__ out, int B)
{
    const int tid = blockIdx.x * blockDim.x + threadIdx.x;
    const int b   = tid >> 3;
    if (b >= B) return;
    const int j   = tid & 7;
    const unsigned FULL = 0xffffffffu;

    const float L2E = 1.4426950408889634f;
    const float NL  = -L2E;         // sigmoid rows: exp(-a) = 2^(NL*a)
    const float PL  = 2.0f * L2E;   // tanh rows:    exp(2a) = 2^(PL*a)

    const int gi = j, gf = j + 8, gg = j + 16, go = j + 24;

    // ---- fold scales into packed weights (one-time) ----
    u64 whIF1[8], whGO1[8], wxIF2[8], wxGO2[8], whIF2[8], whGO2[8];
    #pragma unroll
    for (int k = 0; k < 8; k++) {
        whIF1[k] = pk(NL * w_hh1[gi*8+k], NL * w_hh1[gf*8+k]);
        whGO1[k] = pk(PL * w_hh1[gg*8+k], NL * w_hh1[go*8+k]);
        wxIF2[k] = pk(NL * w_ih2[gi*8+k], NL * w_ih2[gf*8+k]);
        wxGO2[k] = pk(PL * w_ih2[gg*8+k], NL * w_ih2[go*8+k]);
        whIF2[k] = pk(NL * w_hh2[gi*8+k], NL * w_hh2[gf*8+k]);
        whGO2[k] = pk(PL * w_hh2[gg*8+k], NL * w_hh2[go*8+k]);
    }
    const u64 wx1IF = pk(NL * w_ih1[gi], NL * w_ih1[gf]);
    const u64 wx1GO = pk(PL * w_ih1[gg], NL * w_ih1[go]);
    const u64 bIF1  = pk(NL*(b_ih1[gi]+b_hh1[gi]), NL*(b_ih1[gf]+b_hh1[gf]));
    const u64 bGO1  = pk(PL*(b_ih1[gg]+b_hh1[gg]), NL*(b_ih1[go]+b_hh1[go]));
    const u64 bIF2  = pk(NL*(b_ih2[gi]+b_hh2[gi]), NL*(b_ih2[gf]+b_hh2[gf]));
    const u64 bGO2  = pk(PL*(b_ih2[gg]+b_hh2[gg]), NL*(b_ih2[go]+b_hh2[go]));
    const u64 ONE2  = pk(1.0f, 1.0f);

    // ---- state ----
    float c1, c2 = 0.0f;
    u64 H1[8], H2[8];

    const float* xb = x + (size_t)b * T_LEN;

    // ---- prologue: L1 step 0 (h1=c1=0) ----
    {
        const float x0 = __ldg(&xb[0]);
        float ai, af, ag, ao;
        unpk(fma2_(wx1IF, pk(x0, x0), bIF1), ai, af);
        unpk(fma2_(wx1GO, pk(x0, x0), bGO1), ag, ao);
        float Ei = ex2f(ai), Ef = ex2f(af), Eg = ex2f(ag), Eo = ex2f(ao);
        float d1 = 1.f + Ei, d2 = 1.f + Ef, d3 = 1.f + Eg, d4 = 1.f + Eo;
        float rIF = rcpf(d1 * d2), rGO = rcpf(d3 * d4);
        float I = rIF * d2, F = rIF * d1, sg = rGO * d4, O = rGO * d3;
        c1 = I * fmaf(-2.f, sg, 1.f);
        float h1j = O * fmaf(-2.f, rcpf(ex2f(PL * c1) + 1.f), 1.f);
        #pragma unroll
        for (int k = 0; k < 8; k++) {
            float v = __shfl_sync(FULL, h1j, k, 8);
            H1[k] = pk(v, v);
            H2[k] = pk(0.f, 0.f);
        }
    }

    float xt_next = __ldg(&xb[1]);

    // ---- main loop: iteration t does L1(t) and L2(t-1) concurrently ----
    #pragma unroll 1
    for (int t = 1; t < T_LEN; t++) {
        const float xt = xt_next;
        xt_next = __ldg(&xb[(t + 1) & (T_LEN - 1)]);   // wraps harmlessly
        const u64 XT = pk(xt, xt);

        // L1(t) pre-acts: b1 + wx1*x + wh1.H1  (two parallel 4-chains)
        u64 aIF0 = fma2_(wx1IF, XT, bIF1);
        u64 aGO0 = fma2_(wx1GO, XT, bGO1);
        #pragma unroll
        for (int k = 0; k < 4; k++) {
            aIF0 = fma2_(whIF1[k], H1[k], aIF0);
            aGO0 = fma2_(whGO1[k], H1[k], aGO0);
        }
        u64 aIF1 = mul2_(whIF1[4], H1[4]);
        u64 aGO1 = mul2_(whGO1[4], H1[4]);
        #pragma unroll
        for (int k = 5; k < 8; k++) {
            aIF1 = fma2_(whIF1[k], H1[k], aIF1);
            aGO1 = fma2_(whGO1[k], H1[k], aGO1);
        }
        const u64 aIF = add2_(aIF0, aIF1);
        const u64 aGO = add2_(aGO0, aGO1);

        // L2(t-1) pre-acts: b2 + wh2.H2 + wx2.H1  (two parallel 8-chains)
        u64 eIF0 = bIF2, eGO0 = bGO2;
        #pragma unroll
        for (int k = 0; k < 8; k++) {
            eIF0 = fma2_(whIF2[k], H2[k], eIF0);
            eGO0 = fma2_(whGO2[k], H2[k], eGO0);
        }
        u64 eIF1 = mul2_(wxIF2[0], H1[0]);
        u64 eGO1 = mul2_(wxGO2[0], H1[0]);
        #pragma unroll
        for (int k = 1; k < 8; k++) {
            eIF1 = fma2_(wxIF2[k], H1[k], eIF1);
            eGO1 = fma2_(wxGO2[k], H1[k], eGO1);
        }
        const u64 eIF = add2_(eIF0, eIF1);
        const u64 eGO = add2_(eGO0, eGO1);

        // ---- L1 activations (shared rcp per gate pair) ----
        float a_i, a_f, a_g, a_o; unpk(aIF, a_i, a_f); unpk(aGO, a_g, a_o);
        float E1i = ex2f(a_i), E1f = ex2f(a_f), E1g = ex2f(a_g), E1o = ex2f(a_o);
        float d1i, d1f, d1g, d1o;
        unpk(add2_(pk(E1i, E1f), ONE2), d1i, d1f);
        unpk(add2_(pk(E1g, E1o), ONE2), d1g, d1o);
        const float r1IF = rcpf(d1i * d1f), r1GO = rcpf(d1g * d1o);
        float I1, F1, sg1, O1;
        unpk(mul2_(pk(r1IF, r1IF), pk(d1f, d1i)), I1, F1);
        unpk(mul2_(pk(r1GO, r1GO), pk(d1o, d1g)), sg1, O1);
        c1 = fmaf(F1, c1, I1 * fmaf(-2.f, sg1, 1.f));
        const float dc1 = ex2f(PL * c1) + 1.f;

        // ---- L2 activations ----
        float e_i, e_f, e_g, e_o; unpk(eIF, e_i, e_f); unpk(eGO, e_g, e_o);
        float E2i = ex2f(e_i), E2f = ex2f(e_f), E2g = ex2f(e_g), E2o = ex2f(e_o);
        float d2i, d2f, d2g, d2o;
        unpk(add2_(pk(E2i, E2f), ONE2), d2i, d2f);
        unpk(add2_(pk(E2g, E2o), ONE2), d2g, d2o);
        const float r2IF = rcpf(d2i * d2f), r2GO = rcpf(d2g * d2o);
        float I2, F2, sg2, O2;
        unpk(mul2_(pk(r2IF, r2IF), pk(d2f, d2i)), I2, F2);
        unpk(mul2_(pk(r2GO, r2GO), pk(d2o, d2g)), sg2, O2);
        c2 = fmaf(F2, c2, I2 * fmaf(-2.f, sg2, 1.f));
        const float dc2 = ex2f(PL * c2) + 1.f;

        // ---- paired cell tanh (one rcp for both layers) ----
        const float rc = rcpf(dc1 * dc2);
        const float h1j = O1 * fmaf(-2.f, rc * dc2, 1.f);
        const float h2j = O2 * fmaf(-2.f, rc * dc1, 1.f);

        // ---- broadcast h1_t, h2_{t-1} within the 8-lane group ----
        #pragma unroll
        for (int k = 0; k < 8; k++) {
            float v1 = __shfl_sync(FULL, h1j, k, 8);
            float v2 = __shfl_sync(FULL, h2j, k, 8);
            H1[k] = pk(v1, v1);
            H2[k] = pk(v2, v2);
        }
    }

    // ---- epilogue: L2(T-1) ----
    float h2j;
    {
        u64 eIF0 = bIF2, eGO0 = bGO2;
        #pragma unroll
        for (int k = 0; k < 8; k++) {
            eIF0 = fma2_(whIF2[k], H2[k], eIF0);
            eGO0 = fma2_(whGO2[k], H2[k], eGO0);
        }
        u64 eIF1 = mul2_(wxIF2[0], H1[0]);
        u64 eGO1 = mul2_(wxGO2[0], H1[0]);
        #pragma unroll
        for (int k = 1; k < 8; k++) {
            eIF1 = fma2_(wxIF2[k], H1[k], eIF1);
            eGO1 = fma2_(wxGO2[k], H1[k], eGO1);
        }
        float e_i, e_f, e_g, e_o;
        unpk(add2_(eIF0, eIF1), e_i, e_f);
        unpk(add2_(eGO0, eGO1), e_g, e_o);
        float Ei = ex2f(e_i), Ef = ex2f(e_f), Eg = ex2f(e_g), Eo = ex2f(e_o);
        float d1 = 1.f + Ei, d2 = 1.f + Ef, d3 = 1.f + Eg, d4 = 1.f + Eo;
        float rIF = rcpf(d1 * d2), rGO = rcpf(d3 * d4);
        float I = rIF * d2, F = rIF * d1, sg = rGO * d4, O = rGO * d3;
        c2 = fmaf(F, c2, I * fmaf(-2.f, sg, 1.f));
        h2j = O * fmaf(-2.f, rcpf(ex2f(PL * c2) + 1.f), 1.f);
    }

    // ---- fc on final h2 ----
    float h2f[8];
    #pragma unroll
    for (int k = 0; k < 8; k++) h2f[k] = __shfl_sync(FULL, h2j, k, 8);
    if (j < 4) {
        float acc = fc_b[j];
        #pragma unroll
        for (int k = 0; k < 8; k++) acc = fmaf(fc_w[j*8+k], h2f[k], acc);
        out[b*4 + j] = acc;
    }
}

extern "C" void kernel_launch(void* const* d_in, const int* in_sizes, int n_in,
                              void* d_out, int out_size)
{
    const float* x     = (const float*)d_in[0];
    const float* w_ih1 = (const float*)d_in[1];
    const float* w_hh1 = (const float*)d_in[2];
    const float* b_ih1 = (const float*)d_in[3];
    const float* b_hh1 = (const float*)d_in[4];
    const float* w_ih2 = (const float*)d_in[5];
    const float* w_hh2 = (const float*)d_in[6];
    const float* b_ih2 = (const float*)d_in[7];
    const float* b_hh2 = (const float*)d_in[8];
    const float* fc_w  = (const float*)d_in[9];
    const float* fc_b  = (const float*)d_in[10];
    float* out = (float*)d_out;

    const int B = in_sizes[0] / T_LEN;      // 4096
    const int threads = B * 8;
    const int block = 128;
    const int grid = (threads + block - 1) / block;

    lstm2_fused_kernel<<<grid, block>>>(x, w_ih1, w_hh1, b_ih1, b_hh1,
                                        w_ih2, w_hh2, b_ih2, b_hh2,
                                        fc_w, fc_b, out, B);
}